// round 2
// baseline (speedup 1.0000x reference)
#include <cuda_runtime.h>

// DigitCaps routing, shapes fixed by the problem:
//   x [128,1024,16], W [1,16,1024,16,16], B [16,1,1024] -> out [128,16,16] (fp32)
// Kernel 1: u_hat[b][n][c][d] = sum_i W[n][c][d][i] * x[b][c][i]
//           + per-(cblk) partial sums of u_hat over c (for usum)
// Kernel 2: per-b: usum -> scores -> softmax over n -> s -> squash -> out

#define BATCH  128
#define NCAPS  16
#define INCAPS 1024
#define DIMC   16
#define COEF   0.25f   // 1/sqrt(16)

#define K1_CB     16    // c per CTA in kernel 1
#define K1_NCBLK  (INCAPS / K1_CB)   // 64
#define K2_CT     32    // c-tile in kernel 2

// scratch (device globals: allocation-free rule)
__device__ float g_uhat[(size_t)BATCH * NCAPS * INCAPS * DIMC];       // [b][n][c][d], 128 MB
__device__ float g_part[(size_t)K1_NCBLK * BATCH * NCAPS * DIMC];     // [cblk][b][n][d], 8 MB

// ---------------------------------------------------------------------------
// Kernel 1: grid (64, 16) = (cblk, n), 256 threads.
// SMEM: ws[i][c][d] (16x16x16), xs[i][c][b] (16x16x16). Thread tile: 4b x 4d.
// ---------------------------------------------------------------------------
__global__ __launch_bounds__(256) void k1_uhat(const float* __restrict__ x,
                                               const float* __restrict__ W) {
    __shared__ float ws[4096];   // [(i*16+c)*16 + d]
    __shared__ float xs[4096];   // [(i*16+c)*16 + b]  (reused as red[c][b][d])

    const int t    = threadIdx.x;
    const int cblk = blockIdx.x;
    const int n    = blockIdx.y;
    const int c0   = cblk * K1_CB;

    // --- load W[n, c0:c0+16, :, :] (16KB = 1024 float4) -> ws[i][c][d]
    const float4* Wg4 = (const float4*)W;
    const int wbase4 = n * 65536 + c0 * 64;   // float4 units
#pragma unroll
    for (int k = 0; k < 4; k++) {
        int idx4 = t + 256 * k;            // [0, 1024)
        float4 v = Wg4[wbase4 + idx4];
        int flat = idx4 * 4;               // float index within the 4096-float tile
        int c  = flat >> 8;                // [0,16)
        int d  = (flat >> 4) & 15;
        int i0 = flat & 15;                // 0,4,8,12
        ws[((i0 + 0) * 16 + c) * 16 + d] = v.x;
        ws[((i0 + 1) * 16 + c) * 16 + d] = v.y;
        ws[((i0 + 2) * 16 + c) * 16 + d] = v.z;
        ws[((i0 + 3) * 16 + c) * 16 + d] = v.w;
    }
    __syncthreads();

    const int dq = t & 3;
    const int bq = (t >> 2) & 3;
    const int cc = t >> 4;
    const float4* xg4 = (const float4*)x;
    float4* ug4 = (float4*)g_uhat;

    for (int bt = 0; bt < 8; bt++) {
        const int b0 = bt * 16;

        // --- load x[b0:b0+16, c0:c0+16, :] -> xs[i][c][b]
#pragma unroll
        for (int k = 0; k < 4; k++) {
            int idx4 = t + 256 * k;           // 1024 float4 total
            int brow = idx4 >> 6;             // 64 f4 per b-row
            int off  = idx4 & 63;
            float4 v = xg4[(b0 + brow) * 4096 + c0 * 4 + off];
            int cl = off >> 2;
            int i0 = (off & 3) * 4;
            xs[((i0 + 0) * 16 + cl) * 16 + brow] = v.x;
            xs[((i0 + 1) * 16 + cl) * 16 + brow] = v.y;
            xs[((i0 + 2) * 16 + cl) * 16 + brow] = v.z;
            xs[((i0 + 3) * 16 + cl) * 16 + brow] = v.w;
        }
        __syncthreads();

        // --- compute: 4b x 4d outer product over i=16 for c = cc
        float a00=0,a01=0,a02=0,a03=0, a10=0,a11=0,a12=0,a13=0;
        float a20=0,a21=0,a22=0,a23=0, a30=0,a31=0,a32=0,a33=0;
#pragma unroll
        for (int i = 0; i < 16; i++) {
            float4 xv = *(const float4*)&xs[(i * 16 + cc) * 16 + bq * 4];
            float4 wv = *(const float4*)&ws[(i * 16 + cc) * 16 + dq * 4];
            a00 += xv.x * wv.x; a01 += xv.x * wv.y; a02 += xv.x * wv.z; a03 += xv.x * wv.w;
            a10 += xv.y * wv.x; a11 += xv.y * wv.y; a12 += xv.y * wv.z; a13 += xv.y * wv.w;
            a20 += xv.z * wv.x; a21 += xv.z * wv.y; a22 += xv.z * wv.z; a23 += xv.z * wv.w;
            a30 += xv.w * wv.x; a31 += xv.w * wv.y; a32 += xv.w * wv.z; a33 += xv.w * wv.w;
        }

        // --- write u_hat (64B-coalesced chunks)
        {
            int c = c0 + cc;
            int base0 = ((b0 + bq * 4 + 0) * 16 + n) * 4096 + c * 4 + dq;
            int base1 = ((b0 + bq * 4 + 1) * 16 + n) * 4096 + c * 4 + dq;
            int base2 = ((b0 + bq * 4 + 2) * 16 + n) * 4096 + c * 4 + dq;
            int base3 = ((b0 + bq * 4 + 3) * 16 + n) * 4096 + c * 4 + dq;
            ug4[base0] = make_float4(a00, a01, a02, a03);
            ug4[base1] = make_float4(a10, a11, a12, a13);
            ug4[base2] = make_float4(a20, a21, a22, a23);
            ug4[base3] = make_float4(a30, a31, a32, a33);
        }
        __syncthreads();   // done reading xs; safe to reuse as red

        // --- reduce over c within chunk: red[c][b][d]
        float* red = xs;
        *(float4*)&red[(cc * 16 + bq * 4 + 0) * 16 + dq * 4] = make_float4(a00, a01, a02, a03);
        *(float4*)&red[(cc * 16 + bq * 4 + 1) * 16 + dq * 4] = make_float4(a10, a11, a12, a13);
        *(float4*)&red[(cc * 16 + bq * 4 + 2) * 16 + dq * 4] = make_float4(a20, a21, a22, a23);
        *(float4*)&red[(cc * 16 + bq * 4 + 3) * 16 + dq * 4] = make_float4(a30, a31, a32, a33);
        __syncthreads();
        {
            int bb = t >> 4, d = t & 15;
            float s = 0.f;
#pragma unroll
            for (int c2 = 0; c2 < 16; c2++) s += red[c2 * 256 + bb * 16 + d];
            g_part[cblk * 32768 + (b0 + bb) * 256 + n * 16 + d] = s;
        }
        __syncthreads();   // before next tile overwrites red(=xs)
    }
}

// ---------------------------------------------------------------------------
// Kernel 2: grid 128 (one CTA per b), 256 threads.
// SMEM (47360 B): uhs [n:stride656][c:stride20][d] | sco[32][17] | wbf[32][17] | usum[256]
// ---------------------------------------------------------------------------
#define UH_NS 656
#define UH_CS 20

__global__ __launch_bounds__(256) void k2_route(const float* __restrict__ Bb,
                                                float* __restrict__ out) {
    __shared__ float sm[11840];
    float* uhs  = sm;             // 10496 floats
    float* sco  = sm + 10496;     // 544
    float* wbf  = sm + 11040;     // 544
    float* usum = sm + 11584;     // 256

    const int t = threadIdx.x;
    const int b = blockIdx.x;

    // --- usum[n][d] = sum over 64 cblk partials
    {
        const float* p = g_part + b * 256 + t;
        float a0 = 0, a1 = 0, a2 = 0, a3 = 0;
#pragma unroll
        for (int k = 0; k < 64; k += 4) {
            a0 += p[(k + 0) * 32768];
            a1 += p[(k + 1) * 32768];
            a2 += p[(k + 2) * 32768];
            a3 += p[(k + 3) * 32768];
        }
        usum[t] = (a0 + a1) + (a2 + a3);
    }
    __syncthreads();

    // score-phase mapping + register copy of usum row
    const int sn = t >> 4, scs = t & 15;
    float ur[16];
#pragma unroll
    for (int j = 0; j < 16; j++) ur[j] = usum[sn * 16 + j];

    // accumulate-phase mapping
    const int asp = t >> 6, an = (t >> 2) & 15, adq = t & 3;
    float sacc0 = 0, sacc1 = 0, sacc2 = 0, sacc3 = 0;

    const float4* ug4 = (const float4*)g_uhat;

    for (int tile = 0; tile < 32; tile++) {
        const int cb = tile * K2_CT;
        __syncthreads();   // prev accumulate done with uhs/wbf

        // --- load u_hat[b][:, cb:cb+32, :] -> uhs (padded)
#pragma unroll
        for (int k = 0; k < 8; k++) {
            int idx4 = t + 256 * k;         // 2048 f4
            int flat = idx4 * 4;
            int nn = flat >> 9;
            int cl = (flat >> 4) & 31;
            int d0 = flat & 15;             // 0,4,8,12
            float4 v = ug4[(b * 16 + nn) * 4096 + (cb + cl) * 4 + (d0 >> 2)];
            *(float4*)&uhs[nn * UH_NS + cl * UH_CS + d0] = v;
        }
        __syncthreads();

        // --- scores[c][n] = COEF * <usum[n], uhat[n][c]>
#pragma unroll
        for (int p = 0; p < 2; p++) {
            int c = scs + p * 16;
            const float* u = &uhs[sn * UH_NS + c * UH_CS];
            float4 u0 = *(const float4*)(u + 0);
            float4 u1 = *(const float4*)(u + 4);
            float4 u2 = *(const float4*)(u + 8);
            float4 u3 = *(const float4*)(u + 12);
            float dot = u0.x * ur[0] + u0.y * ur[1] + u0.z * ur[2] + u0.w * ur[3]
                      + u1.x * ur[4] + u1.y * ur[5] + u1.z * ur[6] + u1.w * ur[7]
                      + u2.x * ur[8] + u2.y * ur[9] + u2.z * ur[10] + u2.w * ur[11]
                      + u3.x * ur[12] + u3.y * ur[13] + u3.z * ur[14] + u3.w * ur[15];
            sco[c * 17 + sn] = COEF * dot;
        }
        __syncthreads();

        // --- softmax over n (per c) + add B -> wbf[c][n]
        if (t < 32) {
            int c = t;
            float v[16];
            float m = -1e30f;
#pragma unroll
            for (int nn = 0; nn < 16; nn++) { v[nn] = sco[c * 17 + nn]; m = fmaxf(m, v[nn]); }
            float s = 0.f;
#pragma unroll
            for (int nn = 0; nn < 16; nn++) { v[nn] = expf(v[nn] - m); s += v[nn]; }
            float inv = 1.0f / s;
#pragma unroll
            for (int nn = 0; nn < 16; nn++)
                wbf[c * 17 + nn] = v[nn] * inv + Bb[nn * 1024 + cb + c];
        }
        __syncthreads();

        // --- s[n][d] += (c+B) * uhat  (csplit partials in regs)
#pragma unroll
        for (int j = 0; j < 8; j++) {
            int cc = asp * 8 + j;
            float w = wbf[cc * 17 + an];
            float4 uv = *(const float4*)&uhs[an * UH_NS + cc * UH_CS + adq * 4];
            sacc0 += w * uv.x; sacc1 += w * uv.y; sacc2 += w * uv.z; sacc3 += w * uv.w;
        }
    }
    __syncthreads();

    // --- reduce 4 csplit partials (reuse uhs region)
    float* spart = uhs;   // [4][16][16]
    *(float4*)&spart[asp * 256 + an * 16 + adq * 4] = make_float4(sacc0, sacc1, sacc2, sacc3);
    __syncthreads();
    {
        float sv = spart[t] + spart[256 + t] + spart[512 + t] + spart[768 + t];
        sco[t] = sv;   // s_final[n][d]
    }
    __syncthreads();

    // --- squash: scale[n] = (1-exp(-||s||)) / sqrt(||s||^2 + 1e-8)
    if (t < 16) {
        float sq = 0.f;
#pragma unroll
        for (int d = 0; d < 16; d++) { float z = sco[t * 16 + d]; sq += z * z; }
        float norm = sqrtf(sq);
        wbf[t] = (1.0f - expf(-norm)) * rsqrtf(sq + 1e-8f);
    }
    __syncthreads();

    out[b * 256 + t] = wbf[t >> 4] * sco[t];
}

// ---------------------------------------------------------------------------
extern "C" void kernel_launch(void* const* d_in, const int* in_sizes, int n_in,
                              void* d_out, int out_size) {
    const float* x = (const float*)d_in[0];   // [128,1024,16]
    const float* W = (const float*)d_in[1];   // [1,16,1024,16,16]
    const float* B = (const float*)d_in[2];   // [16,1,1024]
    float* out = (float*)d_out;               // [128,16,16]

    k1_uhat<<<dim3(K1_NCBLK, NCAPS), 256>>>(x, W);
    k2_route<<<BATCH, 256>>>(B, out);
}

// round 3
// speedup vs baseline: 1.5331x; 1.5331x over previous
#include <cuda_runtime.h>
#include <cuda_fp16.h>

// DigitCaps routing, shapes fixed by the problem:
//   x [128,1024,16], W [1,16,1024,16,16], B [16,1,1024] -> out [128,16,16] (fp32)
// k1:     u_hat(fp16)[b][n][c][d] = sum_i W[n][c][d][i]*x[b][c][i]; fp32 c-chunk partials of sum_c u_hat
// k_usum: reduce partials -> g_usum[b][n][d] (fp32)
// k2a:    per (b, csplit): scores -> softmax over n -> partial s  (1024 CTAs)
// k2b:    per b: reduce partials, squash, write out

#define BATCH  128
#define NCAPS  16
#define INCAPS 1024
#define DIMC   16
#define COEF   0.25f   // 1/sqrt(16)

#define K1_CB     16
#define K1_NCBLK  (INCAPS / K1_CB)   // 64
#define K2_CT     32                 // c per tile in k2a
#define K2_SPLIT  8                  // c-splits in k2a
#define K2_TILES  (INCAPS / (K2_CT * K2_SPLIT))  // 4

// scratch (device globals: allocation-free rule)
__device__ __half g_uhat[(size_t)BATCH * NCAPS * INCAPS * DIMC];    // [b][n][c][d] fp16, 64 MB
__device__ float  g_part[(size_t)K1_NCBLK * BATCH * NCAPS * DIMC];  // [cblk][b][n*16+d], 8 MB
__device__ float  g_usum[(size_t)BATCH * NCAPS * DIMC];             // [b][n*16+d], 128 KB
__device__ float  g_spart[(size_t)K2_SPLIT * BATCH * NCAPS * DIMC]; // [cs][b][n*16+d], 1 MB

// ---------------------------------------------------------------------------
// Kernel 1: grid (64, 16) = (cblk, n), 256 threads.
// SMEM: ws[i][c][d] (16x16x16), xs[i][c][b] (16x16x16, reused as red[c][b][d]).
// Thread tile: 4b x 4d at c = t>>4. x tile for bt+1 prefetched into registers.
// ---------------------------------------------------------------------------
__global__ __launch_bounds__(256) void k1_uhat(const float* __restrict__ x,
                                               const float* __restrict__ W) {
    __shared__ float ws[4096];
    __shared__ float xs[4096];

    const int t    = threadIdx.x;
    const int cblk = blockIdx.x;
    const int n    = blockIdx.y;
    const int c0   = cblk * K1_CB;

    // --- load W[n, c0:c0+16, :, :] (1024 float4) -> ws[i][c][d]
    const float4* Wg4 = (const float4*)W;
    const int wbase4 = n * 65536 + c0 * 64;
#pragma unroll
    for (int k = 0; k < 4; k++) {
        int idx4 = t + 256 * k;            // [0,1024)
        float4 v = Wg4[wbase4 + idx4];
        int flat = idx4 * 4;
        int c  = flat >> 8;
        int d  = (flat >> 4) & 15;
        int i0 = flat & 15;
        ws[((i0 + 0) * 16 + c) * 16 + d] = v.x;
        ws[((i0 + 1) * 16 + c) * 16 + d] = v.y;
        ws[((i0 + 2) * 16 + c) * 16 + d] = v.z;
        ws[((i0 + 3) * 16 + c) * 16 + d] = v.w;
    }

    const int dq = t & 3;
    const int bq = (t >> 2) & 3;
    const int cc = t >> 4;
    const float4* xg4 = (const float4*)x;

    // prefetch bt=0 x tile into registers
    float4 xv[4];
#pragma unroll
    for (int k = 0; k < 4; k++) {
        int idx4 = t + 256 * k;
        int brow = idx4 >> 6;
        int off  = idx4 & 63;
        xv[k] = xg4[brow * 4096 + c0 * 4 + off];   // b0 = 0
    }
    __syncthreads();   // ws ready

    for (int bt = 0; bt < 8; bt++) {
        const int b0 = bt * 16;

        // --- scatter prefetched x -> xs[i][c][b]
#pragma unroll
        for (int k = 0; k < 4; k++) {
            int idx4 = t + 256 * k;
            int brow = idx4 >> 6;
            int off  = idx4 & 63;
            int cl = off >> 2;
            int i0 = (off & 3) * 4;
            xs[((i0 + 0) * 16 + cl) * 16 + brow] = xv[k].x;
            xs[((i0 + 1) * 16 + cl) * 16 + brow] = xv[k].y;
            xs[((i0 + 2) * 16 + cl) * 16 + brow] = xv[k].z;
            xs[((i0 + 3) * 16 + cl) * 16 + brow] = xv[k].w;
        }
        __syncthreads();

        // --- prefetch next bt (overlaps with compute below)
        {
            int btn = (bt < 7) ? bt + 1 : bt;
            int b0n = btn * 16;
#pragma unroll
            for (int k = 0; k < 4; k++) {
                int idx4 = t + 256 * k;
                int brow = idx4 >> 6;
                int off  = idx4 & 63;
                xv[k] = xg4[(b0n + brow) * 4096 + c0 * 4 + off];
            }
        }

        // --- compute: 4b x 4d outer product over i=16 at c = cc
        float a00=0,a01=0,a02=0,a03=0, a10=0,a11=0,a12=0,a13=0;
        float a20=0,a21=0,a22=0,a23=0, a30=0,a31=0,a32=0,a33=0;
#pragma unroll
        for (int i = 0; i < 16; i++) {
            float4 xr = *(const float4*)&xs[(i * 16 + cc) * 16 + bq * 4];
            float4 wr = *(const float4*)&ws[(i * 16 + cc) * 16 + dq * 4];
            a00 += xr.x * wr.x; a01 += xr.x * wr.y; a02 += xr.x * wr.z; a03 += xr.x * wr.w;
            a10 += xr.y * wr.x; a11 += xr.y * wr.y; a12 += xr.y * wr.z; a13 += xr.y * wr.w;
            a20 += xr.z * wr.x; a21 += xr.z * wr.y; a22 += xr.z * wr.z; a23 += xr.z * wr.w;
            a30 += xr.w * wr.x; a31 += xr.w * wr.y; a32 += xr.w * wr.z; a33 += xr.w * wr.w;
        }

        // --- store u_hat fp16: 8B per b-row, lanes dq cover 32B contiguous
        {
            const int c = c0 + cc;
#define K1_ST(J, A0, A1, A2, A3)                                               \
            {                                                                  \
                size_t hidx = (((size_t)((b0 + bq * 4 + (J)) * 16 + n)) * 1024 \
                               + c) * 16 + dq * 4;                             \
                union { __half2 h[2]; uint2 u; } pk;                           \
                pk.h[0] = __floats2half2_rn(A0, A1);                           \
                pk.h[1] = __floats2half2_rn(A2, A3);                           \
                *(uint2*)(g_uhat + hidx) = pk.u;                               \
            }
            K1_ST(0, a00, a01, a02, a03)
            K1_ST(1, a10, a11, a12, a13)
            K1_ST(2, a20, a21, a22, a23)
            K1_ST(3, a30, a31, a32, a33)
#undef K1_ST
        }
        __syncthreads();   // done reading xs; reuse as red

        // --- reduce over c (fp32 accumulators): red[c][b][d]
        float* red = xs;
        *(float4*)&red[(cc * 16 + bq * 4 + 0) * 16 + dq * 4] = make_float4(a00, a01, a02, a03);
        *(float4*)&red[(cc * 16 + bq * 4 + 1) * 16 + dq * 4] = make_float4(a10, a11, a12, a13);
        *(float4*)&red[(cc * 16 + bq * 4 + 2) * 16 + dq * 4] = make_float4(a20, a21, a22, a23);
        *(float4*)&red[(cc * 16 + bq * 4 + 3) * 16 + dq * 4] = make_float4(a30, a31, a32, a33);
        __syncthreads();
        {
            int bb = t >> 4, d = t & 15;
            float s = 0.f;
#pragma unroll
            for (int c2 = 0; c2 < 16; c2++) s += red[c2 * 256 + bb * 16 + d];
            g_part[cblk * 32768 + (b0 + bb) * 256 + n * 16 + d] = s;
        }
        __syncthreads();
    }
}

// ---------------------------------------------------------------------------
// k_usum: grid 128 (b), 256 threads: usum[b][nd] = sum over 64 cblk partials
// ---------------------------------------------------------------------------
__global__ __launch_bounds__(256) void k_usum() {
    const int t = threadIdx.x, b = blockIdx.x;
    const float* p = g_part + b * 256 + t;
    float a0 = 0, a1 = 0, a2 = 0, a3 = 0;
#pragma unroll
    for (int k = 0; k < 64; k += 4) {
        a0 += p[(k + 0) * 32768];
        a1 += p[(k + 1) * 32768];
        a2 += p[(k + 2) * 32768];
        a3 += p[(k + 3) * 32768];
    }
    g_usum[b * 256 + t] = (a0 + a1) + (a2 + a3);
}

// ---------------------------------------------------------------------------
// k2a: grid (128 b, 8 csplit), 256 threads. 4 tiles of 32 c each.
// SMEM: uhs [n:656][c:20][d] fp32 | sco[32][17] | wbf[32][17]
// ---------------------------------------------------------------------------
#define UH_NS 656
#define UH_CS 20

__global__ __launch_bounds__(256) void k2a_route(const float* __restrict__ Bb) {
    __shared__ float sm[11584];
    float* uhs = sm;            // 10496
    float* sco = sm + 10496;    // 544
    float* wbf = sm + 11040;    // 544

    const int t  = threadIdx.x;
    const int b  = blockIdx.x;
    const int cs = blockIdx.y;

    // score-phase mapping + usum row in registers (L1-cached redundant loads)
    const int sn = t >> 4, scs = t & 15;
    float ur[16];
#pragma unroll
    for (int j = 0; j < 16; j++) ur[j] = g_usum[b * 256 + sn * 16 + j];

    // accumulate-phase mapping
    const int asp = t >> 6, an = (t >> 2) & 15, adq = t & 3;
    float sacc0 = 0, sacc1 = 0, sacc2 = 0, sacc3 = 0;

    const uint4* ug16 = (const uint4*)g_uhat;   // 8 halves per uint4

    for (int tile = 0; tile < K2_TILES; tile++) {
        const int cb = cs * (K2_CT * K2_TILES) + tile * K2_CT;
        __syncthreads();   // prev tile's reads of uhs/wbf done

        // --- load u_hat fp16 [16n][32c][16d] -> uhs fp32 (padded)
#pragma unroll
        for (int k = 0; k < 4; k++) {
            int idx16 = t + 256 * k;          // [0,1024) uint4s
            int flat  = idx16 * 8;            // half index in tile
            int nn = flat >> 9;
            int cl = (flat >> 4) & 31;
            int d0 = flat & 15;               // 0 or 8
            size_t g = ((((size_t)(b * 16 + nn)) * 1024 + cb + cl) * 16 + d0) >> 3;
            uint4 v = ug16[g];
            const __half2* hp = (const __half2*)&v;
            float2 f0 = __half22float2(hp[0]);
            float2 f1 = __half22float2(hp[1]);
            float2 f2 = __half22float2(hp[2]);
            float2 f3 = __half22float2(hp[3]);
            float* dst = &uhs[nn * UH_NS + cl * UH_CS + d0];
            *(float4*)(dst + 0) = make_float4(f0.x, f0.y, f1.x, f1.y);
            *(float4*)(dst + 4) = make_float4(f2.x, f2.y, f3.x, f3.y);
        }
        __syncthreads();

        // --- scores[c][n] = COEF * <usum[n], uhat[n][c]>
#pragma unroll
        for (int p = 0; p < 2; p++) {
            int c = scs + p * 16;
            const float* u = &uhs[sn * UH_NS + c * UH_CS];
            float4 u0 = *(const float4*)(u + 0);
            float4 u1 = *(const float4*)(u + 4);
            float4 u2 = *(const float4*)(u + 8);
            float4 u3 = *(const float4*)(u + 12);
            float dot = u0.x * ur[0] + u0.y * ur[1] + u0.z * ur[2] + u0.w * ur[3]
                      + u1.x * ur[4] + u1.y * ur[5] + u1.z * ur[6] + u1.w * ur[7]
                      + u2.x * ur[8] + u2.y * ur[9] + u2.z * ur[10] + u2.w * ur[11]
                      + u3.x * ur[12] + u3.y * ur[13] + u3.z * ur[14] + u3.w * ur[15];
            sco[c * 17 + sn] = COEF * dot;
        }
        __syncthreads();

        // --- softmax over n (per c) + add B -> wbf[c][n]
        if (t < 32) {
            int c = t;
            float v[16];
            float m = -1e30f;
#pragma unroll
            for (int nn = 0; nn < 16; nn++) { v[nn] = sco[c * 17 + nn]; m = fmaxf(m, v[nn]); }
            float s = 0.f;
#pragma unroll
            for (int nn = 0; nn < 16; nn++) { v[nn] = expf(v[nn] - m); s += v[nn]; }
            float inv = 1.0f / s;
#pragma unroll
            for (int nn = 0; nn < 16; nn++)
                wbf[c * 17 + nn] = v[nn] * inv + Bb[nn * 1024 + cb + c];
        }
        __syncthreads();

        // --- s[n][d] += (c+B) * uhat  (csplit partials in regs)
#pragma unroll
        for (int j = 0; j < 8; j++) {
            int cc2 = asp * 8 + j;
            float w = wbf[cc2 * 17 + an];
            float4 uv = *(const float4*)&uhs[an * UH_NS + cc2 * UH_CS + adq * 4];
            sacc0 += w * uv.x; sacc1 += w * uv.y; sacc2 += w * uv.z; sacc3 += w * uv.w;
        }
    }
    __syncthreads();

    // --- reduce 4 asp partials -> g_spart[cs][b][nd]
    float* spart = uhs;   // [4][16][16]
    *(float4*)&spart[asp * 256 + an * 16 + adq * 4] = make_float4(sacc0, sacc1, sacc2, sacc3);
    __syncthreads();
    g_spart[cs * 32768 + b * 256 + t] =
        spart[t] + spart[256 + t] + spart[512 + t] + spart[768 + t];
}

// ---------------------------------------------------------------------------
// k2b: grid 128 (b), 256 threads: reduce 8 csplits, squash, write out
// ---------------------------------------------------------------------------
__global__ __launch_bounds__(256) void k2b_finish(float* __restrict__ out) {
    __shared__ float sfin[256];
    __shared__ float scale[16];
    const int t = threadIdx.x, b = blockIdx.x;

    const float* p = g_spart + b * 256 + t;
    float a0 = 0, a1 = 0;
#pragma unroll
    for (int k = 0; k < 8; k += 2) {
        a0 += p[(k + 0) * 32768];
        a1 += p[(k + 1) * 32768];
    }
    sfin[t] = a0 + a1;
    __syncthreads();

    if (t < 16) {
        float sq = 0.f;
#pragma unroll
        for (int d = 0; d < 16; d++) { float z = sfin[t * 16 + d]; sq += z * z; }
        float norm = sqrtf(sq);
        scale[t] = (1.0f - expf(-norm)) * rsqrtf(sq + 1e-8f);
    }
    __syncthreads();

    out[b * 256 + t] = scale[t >> 4] * sfin[t];
}

// ---------------------------------------------------------------------------
extern "C" void kernel_launch(void* const* d_in, const int* in_sizes, int n_in,
                              void* d_out, int out_size) {
    const float* x = (const float*)d_in[0];   // [128,1024,16]
    const float* W = (const float*)d_in[1];   // [1,16,1024,16,16]
    const float* B = (const float*)d_in[2];   // [16,1,1024]
    float* out = (float*)d_out;               // [128,16,16]

    k1_uhat<<<dim3(K1_NCBLK, NCAPS), 256>>>(x, W);
    k_usum<<<BATCH, 256>>>();
    k2a_route<<<dim3(BATCH, K2_SPLIT), 256>>>(B);
    k2b_finish<<<BATCH, 256>>>(out);
}